// round 10
// baseline (speedup 1.0000x reference)
#include <cuda_runtime.h>
#include <cuda_fp16.h>
#include <cstdint>

// Problem dims
#define S_DIM   32
#define B_DIM   256
#define IN_DIM  1024
#define OUT_DIM 1024

// ---------------------------------------------------------------------------
// Scratch (device globals; the only sanctioned scratch)
// ---------------------------------------------------------------------------
__device__ __align__(128) __half g_wf16[(size_t)S_DIM * OUT_DIM * IN_DIM];  // 67 MB
__device__ __align__(128) __half g_xf16[(size_t)S_DIM * B_DIM * IN_DIM];    // 17 MB

__device__ __forceinline__ float softplusf(float x) {
    return (x > 15.0f) ? x : log1pf(expf(x));
}

__device__ __forceinline__ uint32_t smem_to_u32(const void* smem_ptr) {
    uint32_t addr;
    asm("{ .reg .u64 tmp; cvta.to.shared.u64 tmp, %1; cvt.u32.u64 %0, tmp; }"
        : "=r"(addr) : "l"(smem_ptr));
    return addr;
}

__device__ __forceinline__ void cp_async16(uint32_t smem_dst, const void* gptr) {
    asm volatile("cp.async.cg.shared.global [%0], [%1], 16;"
                 :: "r"(smem_dst), "l"(gptr) : "memory");
}

__device__ __forceinline__ void ldmatrix_x4(uint32_t r[4], uint32_t addr) {
    asm volatile("ldmatrix.sync.aligned.m8n8.x4.shared.b16 {%0,%1,%2,%3}, [%4];"
                 : "=r"(r[0]), "=r"(r[1]), "=r"(r[2]), "=r"(r[3]) : "r"(addr));
}

__device__ __forceinline__ void mma16816(float c[4],
                                         const uint32_t a[4],
                                         uint32_t b0, uint32_t b1) {
    asm volatile(
        "mma.sync.aligned.m16n8k16.row.col.f32.f16.f16.f32 "
        "{%0,%1,%2,%3}, {%4,%5,%6,%7}, {%8,%9}, {%0,%1,%2,%3};"
        : "+f"(c[0]), "+f"(c[1]), "+f"(c[2]), "+f"(c[3])
        : "r"(a[0]), "r"(a[1]), "r"(a[2]), "r"(a[3]), "r"(b0), "r"(b1));
}

// SW128 swizzle: byte address of 16B-quad (row, colq) in a 128-row x 128B tile.
__device__ __forceinline__ uint32_t sw128(int row, int colq) {
    return ((uint32_t)row << 7) + ((uint32_t)((colq ^ (row & 7)) & 7) << 4);
}

// ---------------------------------------------------------------------------
// Kernel 1 (merged prep):
//   blocks [0,1024):    w_f16[s,o,i] = half(mu + softplus(rho)*eps_w)
//   blocks [1024,9216): x_f16 = half(input)
// ---------------------------------------------------------------------------
__global__ __launch_bounds__(256)
void prep_all_kernel(const float* __restrict__ input,
                     const float* __restrict__ wmu,
                     const float* __restrict__ wrho,
                     const float* __restrict__ epsw)
{
    if (blockIdx.x < 1024) {
        const int q  = blockIdx.x * 256 + threadIdx.x;   // 0..262143 quads
        const int mi = q * 4;

        const float4 m = *reinterpret_cast<const float4*>(wmu + mi);
        const float4 r = *reinterpret_cast<const float4*>(wrho + mi);
        float4 sg;
        sg.x = softplusf(r.x);
        sg.y = softplusf(r.y);
        sg.z = softplusf(r.z);
        sg.w = softplusf(r.w);

        const size_t plane = (size_t)OUT_DIM * IN_DIM;
        #pragma unroll 4
        for (int s = 0; s < S_DIM; ++s) {
            const float4 ew = *reinterpret_cast<const float4*>(epsw + s * plane + mi);
            float w0 = fmaf(sg.x, ew.x, m.x);
            float w1 = fmaf(sg.y, ew.y, m.y);
            float w2 = fmaf(sg.z, ew.z, m.z);
            float w3 = fmaf(sg.w, ew.w, m.w);
            __half2 h0 = __floats2half2_rn(w0, w1);
            __half2 h1 = __floats2half2_rn(w2, w3);
            uint2 o;
            o.x = *reinterpret_cast<unsigned*>(&h0);
            o.y = *reinterpret_cast<unsigned*>(&h1);
            *reinterpret_cast<uint2*>(g_wf16 + s * plane + mi) = o;
        }
    } else {
        const int e4 = (blockIdx.x - 1024) * 256 + threadIdx.x;  // 0..2097151
        const float4 x = *reinterpret_cast<const float4*>(input + (size_t)e4 * 4);
        __half2 h0 = __floats2half2_rn(x.x, x.y);
        __half2 h1 = __floats2half2_rn(x.z, x.w);
        uint2 o;
        o.x = *reinterpret_cast<unsigned*>(&h0);
        o.y = *reinterpret_cast<unsigned*>(&h1);
        reinterpret_cast<uint2*>(g_xf16)[e4] = o;
    }
}

// ---------------------------------------------------------------------------
// Kernel 2: per-sample GEMM via mma.sync (fp16 in / fp32 accum).
// CTA tile M=128 x N=128, K=1024 in 16 chunks of 64. 8 warps (2x4).
// 3-stage cp.async pipeline, one barrier per chunk.
// NEW: XOR-folded ldmatrix addresses (addr(ks) = base ^ (ks<<5)) and
// B-fragment double-buffering across k-steps to hide LDSM latency.
// Grid: (8, 2, 32) = 512 CTAs, 256 threads, 2 CTAs/SM.
// ---------------------------------------------------------------------------
#define KC 64
#define NCHUNK (IN_DIM / KC)          // 16
#define TILE_BYTES (128 * 128)        // 16 KB
#define STAGE_BYTES (2 * TILE_BYTES)  // A + B per stage
#define NSTAGE 3
#define GEMM_DYN_SMEM (1024 + NSTAGE * STAGE_BYTES)

__global__ __launch_bounds__(256, 2)
void gemm_f16_kernel(const float* __restrict__ bias_mu,
                     const float* __restrict__ bias_rho,
                     const float* __restrict__ eps_b,
                     float* __restrict__ out)
{
    extern __shared__ char dynsmem[];
    __shared__ float s_bias[128];

    const int tid = threadIdx.x;
    const int wid = tid >> 5;
    const int lid = tid & 31;
    const int ntile = blockIdx.x;   // 0..7
    const int mtile = blockIdx.y;   // 0..1
    const int s     = blockIdx.z;   // 0..31

    uint32_t base = smem_to_u32(dynsmem);
    base = (base + 1023u) & ~1023u;
    const uint32_t smA0 = base;
    const uint32_t smB0 = base + TILE_BYTES;

    if (tid < 128) {
        const int o = ntile * 128 + tid;
        s_bias[tid] = fmaf(softplusf(bias_rho[o]), eps_b[s * OUT_DIM + o], bias_mu[o]);
    }

    const __half* Ag = g_xf16 + (size_t)(s * B_DIM + mtile * 128) * IN_DIM;
    const __half* Bg = g_wf16 + (size_t)(s * OUT_DIM + ntile * 128) * IN_DIM;

    // Copy slots: 4 quads per tile per thread (full 16KB tile per stage).
    uint32_t cp_dst[4];
    const __half* a_src[4];
    const __half* b_src[4];
    #pragma unroll
    for (int j = 0; j < 4; ++j) {
        const int q   = tid + j * 256;
        const int row = q >> 3;
        const int kq  = q & 7;
        cp_dst[j] = sw128(row, kq);
        a_src[j]  = Ag + (size_t)row * IN_DIM + kq * 8;
        b_src[j]  = Bg + (size_t)row * IN_DIM + kq * 8;
    }

    // Warp tiling: 2 (M) x 4 (N) warps; warp tile 64 x 32.
    const int wm_idx = wid >> 2;
    const int wn_idx = wid & 3;

    // XOR-folded ldmatrix bases: addr(ks) = base ^ (ks<<5).
    // (colq = cq0 + 2ks has disjoint bits: cq0 in bit0, 2ks in bits1-2.)
    uint32_t a_base[4];
    #pragma unroll
    for (int mi = 0; mi < 4; ++mi) {
        const int row = wm_idx * 64 + mi * 16 + (lid & 15);
        a_base[mi] = sw128(row, lid >> 4);
    }
    uint32_t b_base[2];
    #pragma unroll
    for (int g = 0; g < 2; ++g) {
        const int row = wn_idx * 32 + g * 16 + ((lid >> 4) << 3) + (lid & 7);
        b_base[g] = sw128(row, (lid >> 3) & 1);
    }

    float acc[4][4][4];
    #pragma unroll
    for (int mi = 0; mi < 4; ++mi)
        #pragma unroll
        for (int ni = 0; ni < 4; ++ni)
            #pragma unroll
            for (int k = 0; k < 4; ++k)
                acc[mi][ni][k] = 0.0f;

    auto issue_chunk = [&](int c, int st) {
        const uint32_t sa = smA0 + (uint32_t)st * STAGE_BYTES;
        const uint32_t sb = smB0 + (uint32_t)st * STAGE_BYTES;
        #pragma unroll
        for (int j = 0; j < 4; ++j) {
            cp_async16(sa + cp_dst[j], a_src[j] + c * KC);
            cp_async16(sb + cp_dst[j], b_src[j] + c * KC);
        }
        asm volatile("cp.async.commit_group;" ::: "memory");
    };

    issue_chunk(0, 0);
    issue_chunk(1, 1);

    int st = 0;
    for (int c = 0; c < NCHUNK; ++c) {
        if (c == NCHUNK - 1) {
            asm volatile("cp.async.wait_group 0;" ::: "memory");
        } else {
            asm volatile("cp.async.wait_group 1;" ::: "memory");
        }
        __syncthreads();   // chunk c visible; stage (c-1)%3 free for overwrite

        if (c + 2 < NCHUNK) {
            int st2 = st + 2; if (st2 >= NSTAGE) st2 -= NSTAGE;
            issue_chunk(c + 2, st2);
        }

        const uint32_t sa = smA0 + (uint32_t)st * STAGE_BYTES;
        const uint32_t sb = smB0 + (uint32_t)st * STAGE_BYTES;

        // B-fragment double buffer across k-steps.
        uint32_t brP[2][4], brQ[2][4];
        ldmatrix_x4(brP[0], sb + (b_base[0] ^ 0u));
        ldmatrix_x4(brP[1], sb + (b_base[1] ^ 0u));

        #pragma unroll
        for (int ks = 0; ks < 4; ++ks) {
            const uint32_t kx = (uint32_t)(ks << 5);
            uint32_t ar[4][4];
            #pragma unroll
            for (int mi = 0; mi < 4; ++mi)
                ldmatrix_x4(ar[mi], sa + (a_base[mi] ^ kx));

            uint32_t (*cur)[4] = (ks & 1) ? brQ : brP;
            uint32_t (*nxt)[4] = (ks & 1) ? brP : brQ;
            if (ks < 3) {
                const uint32_t kx1 = (uint32_t)((ks + 1) << 5);
                ldmatrix_x4(nxt[0], sb + (b_base[0] ^ kx1));
                ldmatrix_x4(nxt[1], sb + (b_base[1] ^ kx1));
            }

            #pragma unroll
            for (int mi = 0; mi < 4; ++mi) {
                #pragma unroll
                for (int ni = 0; ni < 4; ++ni) {
                    const int g = ni >> 1;
                    const int h = (ni & 1) << 1;
                    mma16816(acc[mi][ni], ar[mi], cur[g][h + 0], cur[g][h + 1]);
                }
            }
        }

        if (++st >= NSTAGE) st -= NSTAGE;
    }

    // Epilogue: add bias, store fp32.
    const int row_in = (lid >> 2);
    const int col_in = (lid & 3) * 2;
    #pragma unroll
    for (int mi = 0; mi < 4; ++mi) {
        const int m0 = mtile * 128 + wm_idx * 64 + mi * 16 + row_in;
        float* orow0 = out + ((size_t)(s * B_DIM + m0)     * OUT_DIM) + ntile * 128;
        float* orow1 = out + ((size_t)(s * B_DIM + m0 + 8) * OUT_DIM) + ntile * 128;
        #pragma unroll
        for (int ni = 0; ni < 4; ++ni) {
            const int lcol = wn_idx * 32 + ni * 8 + col_in;
            const float b0 = s_bias[lcol];
            const float b1 = s_bias[lcol + 1];
            float2 v0, v1;
            v0.x = acc[mi][ni][0] + b0;
            v0.y = acc[mi][ni][1] + b1;
            v1.x = acc[mi][ni][2] + b0;
            v1.y = acc[mi][ni][3] + b1;
            *reinterpret_cast<float2*>(orow0 + lcol) = v0;
            *reinterpret_cast<float2*>(orow1 + lcol) = v1;
        }
    }
}

// ---------------------------------------------------------------------------
// Launch
// ---------------------------------------------------------------------------
extern "C" void kernel_launch(void* const* d_in, const int* in_sizes, int n_in,
                              void* d_out, int out_size)
{
    (void)in_sizes; (void)n_in; (void)out_size;
    const float* input  = (const float*)d_in[0];
    const float* wmu    = (const float*)d_in[1];
    const float* wrho   = (const float*)d_in[2];
    const float* bmu    = (const float*)d_in[3];
    const float* brho   = (const float*)d_in[4];
    const float* epsw   = (const float*)d_in[5];
    const float* epsb   = (const float*)d_in[6];
    float* out = (float*)d_out;

    cudaFuncSetAttribute(gemm_f16_kernel,
                         cudaFuncAttributeMaxDynamicSharedMemorySize,
                         GEMM_DYN_SMEM);

    prep_all_kernel<<<9216, 256>>>(input, wmu, wrho, epsw);
    gemm_f16_kernel<<<dim3(8, 2, 32), 256, GEMM_DYN_SMEM>>>(bmu, brho, epsb, out);
}